// round 4
// baseline (speedup 1.0000x reference)
#include <cuda_runtime.h>
#include <cstdint>

// ---- static problem config ----
#define HMAP      524288u          // 2^19 entries per level
#define HMASK     (HMAP - 1u)
#define NLEVEL    3
#define NPTS      2097152u         // B
#define TBL_ELEMS (NLEVEL * HMAP)  // 1,572,864
#define NPAIRS    (TBL_ELEMS / 2u) // 786,432 pairs per region
#define PRIME1    2654435761u
#define PRIME2    805459861u

// Unified pair-packed table: 4 regions, region p handles tz = 2^(p+1)-1.
// Region p packs entry pairs {b+t, b+K-t} (K = 2^(p+1)-1, group 2^(p+1),
// t in [0, 2^p)) into one aligned float4: (lo.c0, lo.c1, hi.c0, hi.c1),
// lo = member whose low bits (m & K) <= K/2.
__device__ __align__(16) float4 g_tab[4u * NPAIRS];   // 48 MB

// entry m of the flat multi-level table, read from raw triplane layout
__device__ __forceinline__ float2 ent(const float* __restrict__ tri, unsigned m) {
    unsigned p  = m >> 19;
    unsigned mm = m & HMASK;
    const float* base = tri + (size_t)p * (2u * HMAP);
    return make_float2(base[mm], base[mm + HMAP]);
}

// ---------------------------------------------------------------------------
// Pass 1: build the unified pair-packed table.
// ---------------------------------------------------------------------------
__global__ __launch_bounds__(256) void pack_kernel(const float* __restrict__ tri) {
    unsigned n = blockIdx.x * 256u + threadIdx.x;
    if (n >= 4u * NPAIRS) return;
    unsigned p = n / NPAIRS;          // region 0..3
    unsigned j = n - p * NPAIRS;      // pair index inside region
    unsigned K = (2u << p) - 1u;      // 1,3,7,15
    unsigned b = (j >> p) << (p + 1u);
    unsigned t = j & ((1u << p) - 1u);
    float2 lo = ent(tri, b + t);
    float2 hi = ent(tri, b + (K - t));
    g_tab[n] = make_float4(lo.x, lo.y, hi.x, hi.y);
}

// ---------------------------------------------------------------------------
// Pass 2: encode. One thread per query point. Branch-free pair gathers.
// ---------------------------------------------------------------------------
__global__ __launch_bounds__(256) void enc_kernel(const float* __restrict__ xin,
                                                  float2* __restrict__ out) {
    __shared__ float s_in[768];

    const unsigned tid = threadIdx.x;
    // cooperative coalesced float4 load of this block's 768 input floats
    if (tid < 192u) {
        const float4* __restrict__ xin4 = reinterpret_cast<const float4*>(xin);
        reinterpret_cast<float4*>(s_in)[tid] = __ldg(&xin4[blockIdx.x * 192u + tid]);
    }
    __syncthreads();

    const unsigned i = blockIdx.x * 256u + tid;

    const float x0 = (s_in[3u * tid + 0u] + 1.0f) * 0.5f;
    const float y0 = (s_in[3u * tid + 1u] + 1.0f) * 0.5f;
    const float z0 = (s_in[3u * tid + 2u] + 1.0f) * 0.5f;

    float accx = 0.0f, accy = 0.0f;

#pragma unroll
    for (int lv = 0; lv < NLEVEL; lv++) {
        const float scale = (float)((128 << lv) - 1);   // 127, 255, 511

        const float px = x0 * scale + 0.5f;
        const float py = y0 * scale + 0.5f;
        const float pz = z0 * scale + 0.5f;
        const float gx = floorf(px), gy = floorf(py), gz = floorf(pz);
        const float rx = px - gx, ry = py - gy, rz = pz - gz;

        const unsigned ix = (unsigned)gx;
        const unsigned iy = (unsigned)gy;
        const unsigned iz = (unsigned)gz;

        const unsigned hy0 = iy * PRIME1;
        const unsigned hy1 = hy0 + PRIME1;
        const unsigned hz0 = iz * PRIME2;
        const unsigned hz1 = hz0 + PRIME2;

        unsigned r[4];
        r[0] = hy0 ^ hz0;
        r[1] = hy1 ^ hz0;
        r[2] = hy0 ^ hz1;
        r[3] = hy1 ^ hz1;

        const unsigned lvoff = (unsigned)lv * (HMAP / 2u);   // pairs per level
        const unsigned tz     = ix ^ (ix + 1u);              // 2^(k+1)-1
        const bool     fbfar  = tz > 15u;                    // 6.25% of lanes
        const unsigned tzc    = fbfar ? 15u : tz;
        const unsigned k      = (unsigned)__popc(tzc) - 1u;  // region 0..3
        const unsigned half   = tzc >> 1;

        const float4* __restrict__ tp = g_tab + k * NPAIRS + lvoff;

        float2 fa[4], fb[4];   // fa = x-corner ix, fb = x-corner ix+1

#pragma unroll
        for (int c = 0; c < 4; c++) {
            const unsigned m0  = (ix ^ r[c]) & HMASK;
            const unsigned low = m0 & tzc;
            const bool     hib = low > half;
            const unsigned t   = hib ? (tzc - low) : low;
            const unsigned idx = ((m0 & ~tzc) >> 1) + t;
            const float4 q = __ldg(&tp[idx]);
            const float2 qlo = make_float2(q.x, q.y);
            const float2 qhi = make_float2(q.z, q.w);
            fa[c] = hib ? qhi : qlo;
            fb[c] = hib ? qlo : qhi;   // valid partner only when !fbfar
        }

        if (fbfar) {
            // rare: ix with >=4 trailing ones -> fetch fb from region 0 (T1)
            const float4* __restrict__ t1 = g_tab + lvoff;
            const unsigned ix1 = ix + 1u;
#pragma unroll
            for (int c = 0; c < 4; c++) {
                const unsigned m1 = (ix1 ^ r[c]) & HMASK;
                const float4 q = __ldg(&t1[m1 >> 1]);
                fb[c] = (m1 & 1u) ? make_float2(q.z, q.w)
                                  : make_float2(q.x, q.y);
            }
        }

        const float wx0 = 1.0f - rx, wx1 = rx;
        const float wy0 = 1.0f - ry, wy1 = ry;
        const float wz0 = 1.0f - rz, wz1 = rz;

        float wyz[4];
        wyz[0] = wy0 * wz0;
        wyz[1] = wy1 * wz0;
        wyz[2] = wy0 * wz1;
        wyz[3] = wy1 * wz1;

#pragma unroll
        for (int c = 0; c < 4; c++) {
            accx += wyz[c] * (wx0 * fa[c].x + wx1 * fb[c].x);
            accy += wyz[c] * (wx0 * fa[c].y + wx1 * fb[c].y);
        }
    }

    out[i] = make_float2(accx, accy);
}

extern "C" void kernel_launch(void* const* d_in, const int* in_sizes, int n_in,
                              void* d_out, int out_size) {
    const float* tri = (const float*)d_in[0];
    const float* xin = (const float*)d_in[1];
    if (in_sizes[0] != 3145728) {
        tri = (const float*)d_in[1];
        xin = (const float*)d_in[0];
    }
    float2* out = (float2*)d_out;

    pack_kernel<<<(4u * NPAIRS + 255u) / 256u, 256>>>(tri);
    enc_kernel<<<NPTS / 256u, 256>>>(xin, out);
}

// round 5
// speedup vs baseline: 1.5341x; 1.5341x over previous
#include <cuda_runtime.h>
#include <cstdint>

// ---- static problem config ----
#define HMAP      524288u          // 2^19 entries per level
#define HMASK     (HMAP - 1u)
#define NLEVEL    3
#define NPTS      2097152u         // B
#define TBL_ELEMS (NLEVEL * HMAP)  // 1,572,864
#define NPAIRS    (TBL_ELEMS / 2u) // 786,432
#define PRIME1    2654435761u
#define PRIME2    805459861u

// Pair-packed tables. Tk packs entry pairs {m, m^k} into one aligned float4:
//   Tk[((m & ~k)>>1) + t],  t = min(low, k-low), low = m & k
//   slot 0 = member with low <= k/2, slot 1 = the other.
// T1 doubles as the flat float2 table for the scalar fallback.
__device__ __align__(16) float4 g_t1 [NPAIRS];
__device__ __align__(16) float4 g_t3 [NPAIRS];
__device__ __align__(16) float4 g_t7 [NPAIRS];
__device__ __align__(16) float4 g_t15[NPAIRS];

// entry m of the flat multi-level table, read from raw triplane layout
__device__ __forceinline__ float2 ent(const float* __restrict__ tri, unsigned m) {
    unsigned p  = m >> 19;
    unsigned mm = m & HMASK;
    const float* base = tri + (size_t)p * (2u * HMAP);
    return make_float2(base[mm], base[mm + HMAP]);
}

__device__ __forceinline__ float4 pack2(float2 lo, float2 hi) {
    return make_float4(lo.x, lo.y, hi.x, hi.y);
}

// ---------------------------------------------------------------------------
// Pass 1: build all four pair-packed tables from the raw triplane.
// ---------------------------------------------------------------------------
__global__ __launch_bounds__(256) void pack_kernel(const float* __restrict__ tri) {
    unsigned j = blockIdx.x * 256u + threadIdx.x;
    if (j >= NPAIRS) return;

    // T1: pairs {2j, 2j+1}
    g_t1[j] = pack2(ent(tri, 2u * j), ent(tri, 2u * j + 1u));

    // T3: group of 4, pairs {b+a, b+3-a}, a = j&1
    {
        unsigned b = (j >> 1) << 2, a = j & 1u;
        g_t3[j] = pack2(ent(tri, b + a), ent(tri, b + 3u - a));
    }
    // T7: group of 8, pairs {b+t, b+7-t}, t = j&3
    {
        unsigned b = (j >> 2) << 3, t = j & 3u;
        g_t7[j] = pack2(ent(tri, b + t), ent(tri, b + 7u - t));
    }
    // T15: group of 16, pairs {b+t, b+15-t}, t = j&7
    {
        unsigned b = (j >> 3) << 4, t = j & 7u;
        g_t15[j] = pack2(ent(tri, b + t), ent(tri, b + 15u - t));
    }
}

// ---------------------------------------------------------------------------
// Pass 2: encode. One thread per query point. Per-warp coalesced input
// staging through smem (no block barrier).
// ---------------------------------------------------------------------------
__global__ __launch_bounds__(256) void enc_kernel(const float* __restrict__ xin,
                                                  float2* __restrict__ out) {
    __shared__ float s_in[768];

    const unsigned tid  = threadIdx.x;
    const unsigned wrp  = tid >> 5;
    const unsigned lane = tid & 31u;

    // warp w stages its own 32 points = 96 floats = 24 float4s
    if (lane < 24u) {
        const float4* __restrict__ xin4 = reinterpret_cast<const float4*>(xin);
        reinterpret_cast<float4*>(s_in)[wrp * 24u + lane] =
            __ldg(&xin4[blockIdx.x * 192u + wrp * 24u + lane]);
    }
    __syncwarp();

    const unsigned i = blockIdx.x * 256u + tid;

    const float x0 = (s_in[3u * tid + 0u] + 1.0f) * 0.5f;
    const float y0 = (s_in[3u * tid + 1u] + 1.0f) * 0.5f;
    const float z0 = (s_in[3u * tid + 2u] + 1.0f) * 0.5f;

    float accx = 0.0f, accy = 0.0f;

#pragma unroll
    for (int lv = 0; lv < NLEVEL; lv++) {
        const float scale = (float)((128 << lv) - 1);   // 127, 255, 511

        const float px = x0 * scale + 0.5f;
        const float py = y0 * scale + 0.5f;
        const float pz = z0 * scale + 0.5f;
        const float gx = floorf(px), gy = floorf(py), gz = floorf(pz);
        const float rx = px - gx, ry = py - gy, rz = pz - gz;

        const unsigned ix = (unsigned)gx;
        const unsigned iy = (unsigned)gy;
        const unsigned iz = (unsigned)gz;

        const unsigned hy0 = iy * PRIME1;
        const unsigned hy1 = hy0 + PRIME1;
        const unsigned hz0 = iz * PRIME2;
        const unsigned hz1 = hz0 + PRIME2;

        unsigned r[4];
        r[0] = hy0 ^ hz0;
        r[1] = hy1 ^ hz0;
        r[2] = hy0 ^ hz1;
        r[3] = hy1 ^ hz1;

        const unsigned lvoff = (unsigned)lv * (HMAP / 2u);  // in float4 pairs
        const unsigned tz = ix ^ (ix + 1u);                  // 2^(k+1)-1

        float2 fa[4], fb[4];   // fa = x-corner ix, fb = x-corner ix+1

        if (tz <= 15u) {
            const float4* __restrict__ tp =
                (tz == 1u) ? g_t1 : (tz == 3u) ? g_t3 : (tz == 7u) ? g_t7 : g_t15;
            const unsigned half = tz >> 1;
#pragma unroll
            for (int c = 0; c < 4; c++) {
                const unsigned m   = (ix ^ r[c]) & HMASK;
                const unsigned low = m & tz;
                const bool     hib = low > half;
                const unsigned t   = hib ? (tz - low) : low;
                const unsigned idx = ((m & ~tz) >> 1) + t + lvoff;
                const float4 q = __ldg(&tp[idx]);
                const float2 qlo = make_float2(q.x, q.y);
                const float2 qhi = make_float2(q.z, q.w);
                fa[c] = hib ? qhi : qlo;
                fb[c] = hib ? qlo : qhi;
            }
        } else {
            // rare (6.25%): ix with >=4 trailing ones -> 8 scalar gathers
            const float2* __restrict__ t2 =
                reinterpret_cast<const float2*>(g_t1) + (unsigned)lv * HMAP;
            const unsigned ix1 = ix + 1u;
#pragma unroll
            for (int c = 0; c < 4; c++) {
                fa[c] = __ldg(&t2[(ix  ^ r[c]) & HMASK]);
                fb[c] = __ldg(&t2[(ix1 ^ r[c]) & HMASK]);
            }
        }

        const float wx0 = 1.0f - rx, wx1 = rx;
        const float wy0 = 1.0f - ry, wy1 = ry;
        const float wz0 = 1.0f - rz, wz1 = rz;

        float wyz[4];
        wyz[0] = wy0 * wz0;
        wyz[1] = wy1 * wz0;
        wyz[2] = wy0 * wz1;
        wyz[3] = wy1 * wz1;

#pragma unroll
        for (int c = 0; c < 4; c++) {
            accx += wyz[c] * (wx0 * fa[c].x + wx1 * fb[c].x);
            accy += wyz[c] * (wx0 * fa[c].y + wx1 * fb[c].y);
        }
    }

    out[i] = make_float2(accx, accy);
}

extern "C" void kernel_launch(void* const* d_in, const int* in_sizes, int n_in,
                              void* d_out, int out_size) {
    const float* tri = (const float*)d_in[0];
    const float* xin = (const float*)d_in[1];
    if (in_sizes[0] != 3145728) {
        tri = (const float*)d_in[1];
        xin = (const float*)d_in[0];
    }
    float2* out = (float2*)d_out;

    pack_kernel<<<(NPAIRS + 255u) / 256u, 256>>>(tri);
    enc_kernel<<<NPTS / 256u, 256>>>(xin, out);
}

// round 6
// speedup vs baseline: 1.6263x; 1.0601x over previous
#include <cuda_runtime.h>
#include <cstdint>

// ---- static problem config ----
#define HMAP      524288u          // 2^19 entries per level
#define HMASK     (HMAP - 1u)
#define NLEVEL    3
#define NPTS      2097152u         // B
#define TBL_ELEMS (NLEVEL * HMAP)  // 1,572,864
#define NPAIRS    (TBL_ELEMS / 2u) // 786,432
#define PRIME1    2654435761u
#define PRIME2    805459861u

// Pair-packed tables. Tk packs entry pairs {m, m^k} into one aligned float4:
//   Tk[((m & ~k)>>1) + t],  t = min(low, k-low), low = m & k
//   slot 0 = member with low <= k/2, slot 1 = the other.
// T1 doubles as the flat float2 table for the scalar fallback.
__device__ __align__(16) float4 g_t1 [NPAIRS];
__device__ __align__(16) float4 g_t3 [NPAIRS];
__device__ __align__(16) float4 g_t7 [NPAIRS];
__device__ __align__(16) float4 g_t15[NPAIRS];

// entry m of the flat multi-level table, read from raw triplane layout
__device__ __forceinline__ float2 ent(const float* __restrict__ tri, unsigned m) {
    unsigned p  = m >> 19;
    unsigned mm = m & HMASK;
    const float* base = tri + (size_t)p * (2u * HMAP);
    return make_float2(base[mm], base[mm + HMAP]);
}

__device__ __forceinline__ float4 pack2(float2 lo, float2 hi) {
    return make_float4(lo.x, lo.y, hi.x, hi.y);
}

// ---------------------------------------------------------------------------
// Pass 1: build all four pair-packed tables from the raw triplane.
// ---------------------------------------------------------------------------
__global__ __launch_bounds__(256) void pack_kernel(const float* __restrict__ tri) {
    unsigned j = blockIdx.x * 256u + threadIdx.x;
    if (j >= NPAIRS) return;

    g_t1[j] = pack2(ent(tri, 2u * j), ent(tri, 2u * j + 1u));
    {
        unsigned b = (j >> 1) << 2, a = j & 1u;
        g_t3[j] = pack2(ent(tri, b + a), ent(tri, b + 3u - a));
    }
    {
        unsigned b = (j >> 2) << 3, t = j & 3u;
        g_t7[j] = pack2(ent(tri, b + t), ent(tri, b + 7u - t));
    }
    {
        unsigned b = (j >> 3) << 4, t = j & 7u;
        g_t15[j] = pack2(ent(tri, b + t), ent(tri, b + 15u - t));
    }
}

// ---------------------------------------------------------------------------
// Pass 2: encode. TWO points per thread: coalesced aligned LDG.64 inputs,
// one float4 store, per-level interleaved gathers with deferred selects.
// ---------------------------------------------------------------------------
__global__ __launch_bounds__(256) void enc_kernel(const float* __restrict__ xin,
                                                  float4* __restrict__ out) {
    const unsigned t = blockIdx.x * 256u + threadIdx.x;   // pair index < NPTS/2

    const float2* __restrict__ x2 = reinterpret_cast<const float2*>(xin);
    const float2 A  = __ldg(&x2[3u * t + 0u]);   // p0.x p0.y
    const float2 Bv = __ldg(&x2[3u * t + 1u]);   // p0.z p1.x
    const float2 Cv = __ldg(&x2[3u * t + 2u]);   // p1.y p1.z

    float cx[2], cy[2], cz[2];
    cx[0] = (A.x  + 1.0f) * 0.5f;  cy[0] = (A.y  + 1.0f) * 0.5f;  cz[0] = (Bv.x + 1.0f) * 0.5f;
    cx[1] = (Bv.y + 1.0f) * 0.5f;  cy[1] = (Cv.x + 1.0f) * 0.5f;  cz[1] = (Cv.y + 1.0f) * 0.5f;

    float accx[2] = {0.0f, 0.0f}, accy[2] = {0.0f, 0.0f};

#pragma unroll
    for (int lv = 0; lv < NLEVEL; lv++) {
        const float scale = (float)((128 << lv) - 1);   // 127, 255, 511

        float4 q[2][4];          // raw pair loads (selection deferred)
        bool   hib[2][4];
        float  rx[2], ry[2], rz[2];

        // ---- gather phase: both points' loads issued before any consumption
#pragma unroll
        for (int u = 0; u < 2; u++) {
            const float px = cx[u] * scale + 0.5f;
            const float py = cy[u] * scale + 0.5f;
            const float pz = cz[u] * scale + 0.5f;
            const float gx = floorf(px), gy = floorf(py), gz = floorf(pz);
            rx[u] = px - gx; ry[u] = py - gy; rz[u] = pz - gz;

            const unsigned ix = (unsigned)gx;
            const unsigned iy = (unsigned)gy;
            const unsigned iz = (unsigned)gz;

            const unsigned hy0 = iy * PRIME1;
            const unsigned hy1 = hy0 + PRIME1;
            const unsigned hz0 = iz * PRIME2;
            const unsigned hz1 = hz0 + PRIME2;

            unsigned rr[4];
            rr[0] = hy0 ^ hz0;
            rr[1] = hy1 ^ hz0;
            rr[2] = hy0 ^ hz1;
            rr[3] = hy1 ^ hz1;

            const unsigned lvoff = (unsigned)lv * (HMAP / 2u);
            const unsigned tz = ix ^ (ix + 1u);

            if (tz <= 15u) {
                const float4* __restrict__ tp =
                    (tz == 1u) ? g_t1 : (tz == 3u) ? g_t3 : (tz == 7u) ? g_t7 : g_t15;
                const unsigned half = tz >> 1;
#pragma unroll
                for (int c = 0; c < 4; c++) {
                    const unsigned m   = (ix ^ rr[c]) & HMASK;
                    const unsigned low = m & tz;
                    const bool     hb  = low > half;
                    const unsigned s   = hb ? (tz - low) : low;
                    q[u][c]   = __ldg(&tp[((m & ~tz) >> 1) + s + lvoff]);
                    hib[u][c] = hb;
                }
            } else {
                // rare (6.25%): ix with >=4 trailing ones -> 8 scalar gathers
                const float2* __restrict__ t2 =
                    reinterpret_cast<const float2*>(g_t1) + (unsigned)lv * HMAP;
                const unsigned ix1 = ix + 1u;
#pragma unroll
                for (int c = 0; c < 4; c++) {
                    const float2 fa = __ldg(&t2[(ix  ^ rr[c]) & HMASK]);
                    const float2 fb = __ldg(&t2[(ix1 ^ rr[c]) & HMASK]);
                    q[u][c]   = make_float4(fa.x, fa.y, fb.x, fb.y);
                    hib[u][c] = false;
                }
            }
        }

        // ---- math phase: selects + trilinear accumulate
#pragma unroll
        for (int u = 0; u < 2; u++) {
            const float wx0 = 1.0f - rx[u], wx1 = rx[u];
            const float wy0 = 1.0f - ry[u], wy1 = ry[u];
            const float wz0 = 1.0f - rz[u], wz1 = rz[u];
            float wyz[4];
            wyz[0] = wy0 * wz0;
            wyz[1] = wy1 * wz0;
            wyz[2] = wy0 * wz1;
            wyz[3] = wy1 * wz1;
#pragma unroll
            for (int c = 0; c < 4; c++) {
                const bool  hb  = hib[u][c];
                const float fax = hb ? q[u][c].z : q[u][c].x;
                const float fay = hb ? q[u][c].w : q[u][c].y;
                const float fbx = hb ? q[u][c].x : q[u][c].z;
                const float fby = hb ? q[u][c].y : q[u][c].w;
                accx[u] += wyz[c] * (wx0 * fax + wx1 * fbx);
                accy[u] += wyz[c] * (wx0 * fay + wx1 * fby);
            }
        }
    }

    out[t] = make_float4(accx[0], accy[0], accx[1], accy[1]);
}

extern "C" void kernel_launch(void* const* d_in, const int* in_sizes, int n_in,
                              void* d_out, int out_size) {
    const float* tri = (const float*)d_in[0];
    const float* xin = (const float*)d_in[1];
    if (in_sizes[0] != 3145728) {
        tri = (const float*)d_in[1];
        xin = (const float*)d_in[0];
    }
    float4* out = (float4*)d_out;

    pack_kernel<<<(NPAIRS + 255u) / 256u, 256>>>(tri);
    enc_kernel<<<NPTS / 2u / 256u, 256>>>(xin, out);
}

// round 7
// speedup vs baseline: 1.6347x; 1.0051x over previous
#include <cuda_runtime.h>
#include <cstdint>

// ---- static problem config ----
#define HMAP      524288u          // 2^19 entries per level
#define HMASK     (HMAP - 1u)
#define NLEVEL    3
#define NPTS      2097152u         // B
#define TBL_ELEMS (NLEVEL * HMAP)  // 1,572,864
#define NPAIRS    (TBL_ELEMS / 2u) // 786,432
#define PRIME1    2654435761u
#define PRIME2    805459861u

// Pair-packed tables. Tk packs entry pairs {m, m^k} into one aligned float4:
//   Tk[((m & ~k)>>1) + t],  t = min(low, k-low), low = m & k
//   slot lo = member with (m & k) <= k/2; float4 = (lo.c0, lo.c1, hi.c0, hi.c1)
// T1 doubles as the flat float2 table for the scalar fallback.
__device__ __align__(16) float4 g_t1 [NPAIRS];
__device__ __align__(16) float4 g_t3 [NPAIRS];
__device__ __align__(16) float4 g_t7 [NPAIRS];
__device__ __align__(16) float4 g_t15[NPAIRS];
__device__ __align__(16) float4 g_t31[NPAIRS];

// entry m of the flat multi-level table, read from raw triplane layout
__device__ __forceinline__ float2 ent(const float* __restrict__ tri, unsigned m) {
    unsigned p  = m >> 19;
    unsigned mm = m & HMASK;
    const float* base = tri + (size_t)p * (2u * HMAP);
    return make_float2(base[mm], base[mm + HMAP]);
}

__device__ __forceinline__ float4 pack2(float2 lo, float2 hi) {
    return make_float4(lo.x, lo.y, hi.x, hi.y);
}

// ---------------------------------------------------------------------------
// Pass 1: build all five pair-packed tables from the raw triplane.
// ---------------------------------------------------------------------------
__global__ __launch_bounds__(256) void pack_kernel(const float* __restrict__ tri) {
    unsigned j = blockIdx.x * 256u + threadIdx.x;
    if (j >= NPAIRS) return;

    g_t1[j] = pack2(ent(tri, 2u * j), ent(tri, 2u * j + 1u));
    {   // K=3, group 4
        unsigned b = (j >> 1) << 2, t = j & 1u;
        g_t3[j] = pack2(ent(tri, b + t), ent(tri, b + 3u - t));
    }
    {   // K=7, group 8
        unsigned b = (j >> 2) << 3, t = j & 3u;
        g_t7[j] = pack2(ent(tri, b + t), ent(tri, b + 7u - t));
    }
    {   // K=15, group 16
        unsigned b = (j >> 3) << 4, t = j & 7u;
        g_t15[j] = pack2(ent(tri, b + t), ent(tri, b + 15u - t));
    }
    {   // K=31, group 32
        unsigned b = (j >> 4) << 5, t = j & 15u;
        g_t31[j] = pack2(ent(tri, b + t), ent(tri, b + 31u - t));
    }
}

// ---------------------------------------------------------------------------
// Pass 2: encode. TWO points per thread; coalesced LDG.64 inputs, one float4
// store. Selection folded into the x-weight: contribution per corner =
//   wyz * ( wa*(lo - hi) + hi ),  wa = hib ? rx : 1-rx.
// ---------------------------------------------------------------------------
__global__ __launch_bounds__(256) void enc_kernel(const float* __restrict__ xin,
                                                  float4* __restrict__ out) {
    const unsigned t = blockIdx.x * 256u + threadIdx.x;   // pair index < NPTS/2

    const float2* __restrict__ x2 = reinterpret_cast<const float2*>(xin);
    const float2 A  = __ldg(&x2[3u * t + 0u]);   // p0.x p0.y
    const float2 Bv = __ldg(&x2[3u * t + 1u]);   // p0.z p1.x
    const float2 Cv = __ldg(&x2[3u * t + 2u]);   // p1.y p1.z

    float cx[2], cy[2], cz[2];
    cx[0] = (A.x  + 1.0f) * 0.5f;  cy[0] = (A.y  + 1.0f) * 0.5f;  cz[0] = (Bv.x + 1.0f) * 0.5f;
    cx[1] = (Bv.y + 1.0f) * 0.5f;  cy[1] = (Cv.x + 1.0f) * 0.5f;  cz[1] = (Cv.y + 1.0f) * 0.5f;

    float accx[2] = {0.0f, 0.0f}, accy[2] = {0.0f, 0.0f};

#pragma unroll
    for (int lv = 0; lv < NLEVEL; lv++) {
        const float scale = (float)((128 << lv) - 1);   // 127, 255, 511

        float4 q [2][4];   // raw pair loads: (lo.c0, lo.c1, hi.c0, hi.c1)
        float  wa[2][4];   // x-weight applied to the .xy (lo) half
        float  ry[2], rz[2];

        // ---- gather phase: both points' loads issued before any consumption
#pragma unroll
        for (int u = 0; u < 2; u++) {
            const float px = cx[u] * scale + 0.5f;
            const float py = cy[u] * scale + 0.5f;
            const float pz = cz[u] * scale + 0.5f;
            const float gx = floorf(px), gy = floorf(py), gz = floorf(pz);
            const float rx = px - gx;
            ry[u] = py - gy; rz[u] = pz - gz;
            const float wx0 = 1.0f - rx, wx1 = rx;

            const unsigned ix = (unsigned)gx;
            const unsigned iy = (unsigned)gy;
            const unsigned iz = (unsigned)gz;

            const unsigned hy0 = iy * PRIME1;
            const unsigned hy1 = hy0 + PRIME1;
            const unsigned hz0 = iz * PRIME2;
            const unsigned hz1 = hz0 + PRIME2;

            unsigned rr[4];
            rr[0] = hy0 ^ hz0;
            rr[1] = hy1 ^ hz0;
            rr[2] = hy0 ^ hz1;
            rr[3] = hy1 ^ hz1;

            const unsigned lvoff = (unsigned)lv * (HMAP / 2u);
            const unsigned tz = ix ^ (ix + 1u);

            if (tz <= 31u) {
                const float4* __restrict__ tp =
                    (tz == 1u) ? g_t1 : (tz == 3u) ? g_t3 : (tz == 7u) ? g_t7
                                      : (tz == 15u) ? g_t15 : g_t31;
                const unsigned half = tz >> 1;
#pragma unroll
                for (int c = 0; c < 4; c++) {
                    const unsigned m   = (ix ^ rr[c]) & HMASK;
                    const unsigned low = m & tz;
                    const bool     hb  = low > half;
                    const unsigned s   = hb ? (tz - low) : low;
                    q[u][c]  = __ldg(&tp[((m & ~tz) >> 1) + s + lvoff]);
                    wa[u][c] = hb ? wx1 : wx0;   // weight on lo half
                }
            } else {
                // rare (~3.1%): ix with >=5 trailing ones -> 8 scalar gathers
                const float2* __restrict__ t2 =
                    reinterpret_cast<const float2*>(g_t1) + (unsigned)lv * HMAP;
                const unsigned ix1 = ix + 1u;
#pragma unroll
                for (int c = 0; c < 4; c++) {
                    const float2 fa = __ldg(&t2[(ix  ^ rr[c]) & HMASK]);
                    const float2 fb = __ldg(&t2[(ix1 ^ rr[c]) & HMASK]);
                    q[u][c]  = make_float4(fa.x, fa.y, fb.x, fb.y);
                    wa[u][c] = wx0;              // lo = x-corner ix
                }
            }
        }

        // ---- math phase
#pragma unroll
        for (int u = 0; u < 2; u++) {
            const float wy0 = 1.0f - ry[u], wy1 = ry[u];
            const float wz0 = 1.0f - rz[u], wz1 = rz[u];
            float wyz[4];
            wyz[0] = wy0 * wz0;
            wyz[1] = wy1 * wz0;
            wyz[2] = wy0 * wz1;
            wyz[3] = wy1 * wz1;
#pragma unroll
            for (int c = 0; c < 4; c++) {
                const float w = wa[u][c];
                // wa*lo + (1-wa)*hi  ==  wa*(lo-hi) + hi
                accx[u] += wyz[c] * fmaf(w, q[u][c].x - q[u][c].z, q[u][c].z);
                accy[u] += wyz[c] * fmaf(w, q[u][c].y - q[u][c].w, q[u][c].w);
            }
        }
    }

    out[t] = make_float4(accx[0], accy[0], accx[1], accy[1]);
}

extern "C" void kernel_launch(void* const* d_in, const int* in_sizes, int n_in,
                              void* d_out, int out_size) {
    const float* tri = (const float*)d_in[0];
    const float* xin = (const float*)d_in[1];
    if (in_sizes[0] != 3145728) {
        tri = (const float*)d_in[1];
        xin = (const float*)d_in[0];
    }
    float4* out = (float4*)d_out;

    pack_kernel<<<(NPAIRS + 255u) / 256u, 256>>>(tri);
    enc_kernel<<<NPTS / 2u / 256u, 256>>>(xin, out);
}